// round 16
// baseline (speedup 1.0000x reference)
#include <cuda_runtime.h>
#include <cuda_bf16.h>
#include <cstdint>

#define NN 1024
#define TOPK 16
#define NPAIR 272           // 256 pos (c_hi,t) pairs + 16 rep c_hi slices
#define KK (NPAIR * 32)     // 8704
#define MM 2048             // (b, w)
#define NCH64 (KK / 64)     // 136 K-chunks of 64

// Scratch (device globals: allocation-free per harness rules)
__device__ int            g_row[NPAIR * 64];
__device__ __nv_bfloat16  g_Ah[(size_t)MM * KK];
__device__ __nv_bfloat16  g_Al[(size_t)MM * KK];
__device__ __nv_bfloat16  g_Bh[(size_t)NN * KK];
__device__ __nv_bfloat16  g_Bl[(size_t)NN * KK];

__device__ __forceinline__ uint32_t smem_u32(const void* p) {
    uint32_t a;
    asm("{ .reg .u64 t; cvta.to.shared.u64 t, %1; cvt.u32.u64 %0, t; }"
        : "=r"(a) : "l"(p));
    return a;
}
__device__ __forceinline__ void split_bf16(float x, __nv_bfloat16& h, __nv_bfloat16& l) {
    h = __float2bfloat16(x);
    l = __float2bfloat16(x - __bfloat162float(h));
}
__device__ __forceinline__ uint32_t pack_bf2(__nv_bfloat16 a, __nv_bfloat16 b) {
    __nv_bfloat162 v(a, b);
    return *(uint32_t*)&v;
}

// ---------------------------------------------------------------------------
// Kernel 1: exact top-16 per row (ties -> lowest index) + g_row emission.
// ---------------------------------------------------------------------------
__global__ __launch_bounds__(1024) void topk_kernel(const float* __restrict__ f1) {
    __shared__ float wv[32];
    __shared__ int   wi[32];
    __shared__ int   s_best;
    __shared__ int   s_idx[TOPK];
    const int n = blockIdx.x, tid = threadIdx.x;
    const int lane = tid & 31, w = tid >> 5;
    float v = f1[n * NN + tid];
    const float NEG_INF = __int_as_float(0xff800000);

    for (int it = 0; it < TOPK; ++it) {
        float rv = v; int ri = tid;
#pragma unroll
        for (int s = 16; s > 0; s >>= 1) {
            float ov = __shfl_down_sync(0xffffffffu, rv, s);
            int   oi = __shfl_down_sync(0xffffffffu, ri, s);
            if (ov > rv || (ov == rv && oi < ri)) { rv = ov; ri = oi; }
        }
        if (lane == 0) { wv[w] = rv; wi[w] = ri; }
        __syncthreads();
        if (w == 0) {
            float rv2 = wv[lane]; int ri2 = wi[lane];
#pragma unroll
            for (int s = 16; s > 0; s >>= 1) {
                float ov = __shfl_down_sync(0xffffffffu, rv2, s);
                int   oi = __shfl_down_sync(0xffffffffu, ri2, s);
                if (ov > rv2 || (ov == rv2 && oi < ri2)) { rv2 = ov; ri2 = oi; }
            }
            if (lane == 0) { s_idx[it] = ri2; s_best = ri2; }
        }
        __syncthreads();
        if (tid == s_best) v = NEG_INF;
    }
    const int b = n >> 4, c_hi = n & 15;
    if (tid < TOPK) g_row[(c_hi * 16 + tid) * 64 + b] = s_idx[tid];
    if (tid == TOPK) g_row[(256 + c_hi) * 64 + b] = n;
}

// ---------------------------------------------------------------------------
// Kernel 2: build split-bf16 B [NN, KK] K-major, float4 reads + 8B stores.
// ---------------------------------------------------------------------------
__global__ __launch_bounds__(512) void build_B_kernel(const float* __restrict__ conv_w) {
    const int o = blockIdx.x;
    const float* cw = conv_w + (size_t)o * 16384;
    for (int k0 = threadIdx.x * 4; k0 < KK; k0 += 2048) {
        int pair = k0 >> 5, j = k0 & 31, c2 = j >> 4, h = j & 15;
        float4 v;
        if (pair < 256) {
            int ch = pair >> 4, t = pair & 15;
            v = *(const float4*)(cw + (ch * 64 + t * 4 + 2 + c2) * 16 + h);
        } else {
            int ch = pair - 256;
            v = make_float4(0.f, 0.f, 0.f, 0.f);
#pragma unroll
            for (int t = 0; t < 16; ++t) {
                float4 u = *(const float4*)(cw + (ch * 64 + t * 4 + c2) * 16 + h);
                v.x += u.x; v.y += u.y; v.z += u.z; v.w += u.w;
            }
        }
        __nv_bfloat16 hh[4], ll[4];
        split_bf16(v.x, hh[0], ll[0]); split_bf16(v.y, hh[1], ll[1]);
        split_bf16(v.z, hh[2], ll[2]); split_bf16(v.w, hh[3], ll[3]);
        uint2 ph = make_uint2(pack_bf2(hh[0], hh[1]), pack_bf2(hh[2], hh[3]));
        uint2 pl = make_uint2(pack_bf2(ll[0], ll[1]), pack_bf2(ll[2], ll[3]));
        *(uint2*)&g_Bh[(size_t)o * KK + k0] = ph;
        *(uint2*)&g_Bl[(size_t)o * KK + k0] = pl;
    }
}

// ---------------------------------------------------------------------------
// Kernel 3: build split-bf16 A [MM, KK] K-major, coalesced 16B stores.
// ---------------------------------------------------------------------------
#define SP2 1056   // 32 * 33 floats per staged row

__global__ __launch_bounds__(256) void build_A_kernel(const float* __restrict__ f1) {
    __shared__ float s[8 * SP2];
    const int pg = blockIdx.x, b = blockIdx.y, t = threadIdx.x;
    {
        const int pi = t >> 5, c32 = t & 31;
        const int r = g_row[(pg * 8 + pi) * 64 + b];
        const float4* src = (const float4*)(f1 + (size_t)r * 1024);
        const int jb = c32 >> 3;
        const int w0 = (c32 & 7) * 4;
#pragma unroll
        for (int q = 0; q < 8; ++q) {
            float4 v = src[c32 + q * 32];
            float* dst = &s[pi * SP2 + (jb + 4 * q) * 33 + w0];
            dst[0] = v.x; dst[1] = v.y; dst[2] = v.z; dst[3] = v.w;
        }
    }
    __syncthreads();
    const int w = t >> 3, pp = (t >> 2) & 1, jc = t & 3, j0 = jc * 8;
#pragma unroll
    for (int q = 0; q < 4; ++q) {
        const int pi = q * 2 + pp;
        __nv_bfloat16 h[8], l[8];
#pragma unroll
        for (int d = 0; d < 8; ++d) {
            float v = s[pi * SP2 + (j0 + d) * 33 + w];
            split_bf16(v, h[d], l[d]);
        }
        uint4 ph = make_uint4(pack_bf2(h[0], h[1]), pack_bf2(h[2], h[3]),
                              pack_bf2(h[4], h[5]), pack_bf2(h[6], h[7]));
        uint4 pl = make_uint4(pack_bf2(l[0], l[1]), pack_bf2(l[2], l[3]),
                              pack_bf2(l[4], l[5]), pack_bf2(l[6], l[7]));
        const size_t dst = (size_t)(b * 32 + w) * KK + (pg * 8 + pi) * 32 + j0;
        *(uint4*)&g_Ah[dst] = ph;
        *(uint4*)&g_Al[dst] = pl;
    }
}

// ---------------------------------------------------------------------------
// Kernel 4: HMMA GEMM (locked best config, R12/R14).
// C = AhBh + AhBl + AlBh, bias+relu. CTA 128x128, 8 warps (2x4), warp 64x32,
// BK=64, 3-stage cp.async (batched 16 CP16 at chunk top), frag double-buffer
// + cross-chunk kk0 prefetch.
// ---------------------------------------------------------------------------
#define TILE_B 16384
#define STAGE_B 65536
#define DSMEM_B (3 * STAGE_B)

#define LDSM_X4(R, ADDR) \
    asm volatile("ldmatrix.sync.aligned.m8n8.x4.shared.b16 {%0,%1,%2,%3}, [%4];" \
        : "=r"((R)[0]), "=r"((R)[1]), "=r"((R)[2]), "=r"((R)[3]) : "r"(ADDR))
#define MMA16816(C, A, B) \
    asm volatile("mma.sync.aligned.m16n8k16.row.col.f32.bf16.bf16.f32 " \
        "{%0,%1,%2,%3}, {%4,%5,%6,%7}, {%8,%9}, {%0,%1,%2,%3};" \
        : "+f"((C)[0]), "+f"((C)[1]), "+f"((C)[2]), "+f"((C)[3]) \
        : "r"((A)[0]), "r"((A)[1]), "r"((A)[2]), "r"((A)[3]), \
          "r"((B)[0]), "r"((B)[1]))
#define CP16(DST, SRC) \
    asm volatile("cp.async.cg.shared.global [%0], [%1], 16;" \
        :: "r"(DST), "l"(SRC) : "memory")

__global__ __launch_bounds__(256, 1) void hmma_gemm_kernel(
    const float* __restrict__ conv_b, float* __restrict__ out) {
    extern __shared__ __align__(128) char dsm[];
    __shared__ float s_bias[128];

    const int tid = threadIdx.x, lane = tid & 31, wid = tid >> 5;
    const int m0 = blockIdx.y * 128, n0 = blockIdx.x * 128;
    const int wm = wid >> 2, wn = wid & 3;
    const uint32_t sbase = smem_u32(dsm);
    if (tid < 128) s_bias[tid] = conv_b[n0 + tid];

    // ---- cp.async mapping: 16 x 16B chunks per thread per stage ----
    const __nv_bfloat16* gp[16];
    uint32_t doff[16];
#pragma unroll
    for (int i = 0; i < 16; ++i) {
        int cid = tid + i * 256;
        int tile = cid >> 10, row = (cid >> 3) & 127, ch = cid & 7;
        const __nv_bfloat16* base =
            (tile == 0) ? g_Ah + (size_t)(m0 + row) * KK :
            (tile == 1) ? g_Al + (size_t)(m0 + row) * KK :
            (tile == 2) ? g_Bh + (size_t)(n0 + row) * KK :
                          g_Bl + (size_t)(n0 + row) * KK;
        gp[i] = base + ch * 8;
        doff[i] = tile * TILE_B + row * 128 + ((ch ^ (row & 7)) * 16);
    }

    // ---- ldmatrix lane constants ----
    const int aq  = lane >> 3;
    const int aml = wm * 64 + (aq & 1) * 8 + (lane & 7);
    const int acp = aq >> 1;
    const int as  = aml & 7;
    const int bnl4 = wn * 32 + ((lane >> 4) & 1) * 8 + (lane & 7);
    const int bq4  = (lane >> 3) & 1;
    const int bs4  = bnl4 & 7;

    float acc[4][4][4];
#pragma unroll
    for (int mi = 0; mi < 4; ++mi)
#pragma unroll
        for (int ni = 0; ni < 4; ++ni)
#pragma unroll
            for (int r = 0; r < 4; ++r) acc[mi][ni][r] = 0.f;

    uint32_t ah[2][4][4], al[2][4][4], bh[2][2][4], bl[2][2][4];

    auto ld_frags = [&](int fb, uint32_t st, int kk) {
        const uint32_t aoff = aml * 128 + (((kk * 2 + acp) ^ as) * 16);
        const uint32_t boff = bnl4 * 128 + (((kk * 2 + bq4) ^ bs4) * 16);
#pragma unroll
        for (int mi = 0; mi < 4; ++mi) LDSM_X4(ah[fb][mi], st + aoff + mi * 2048);
#pragma unroll
        for (int mi = 0; mi < 4; ++mi) LDSM_X4(al[fb][mi], st + TILE_B + aoff + mi * 2048);
#pragma unroll
        for (int nj = 0; nj < 2; ++nj) LDSM_X4(bh[fb][nj], st + 2 * TILE_B + boff + nj * 2048);
#pragma unroll
        for (int nj = 0; nj < 2; ++nj) LDSM_X4(bl[fb][nj], st + 3 * TILE_B + boff + nj * 2048);
    };

    // ---- prologue: stages 0 and 1; wait for BOTH (kk3 of chunk 0 prefetches
    //      chunk 1 kk0 from stage 1, so stage 1 must be complete) ----
#pragma unroll
    for (int i = 0; i < 16; ++i) CP16(sbase + doff[i], gp[i]);
    asm volatile("cp.async.commit_group;" ::: "memory");
#pragma unroll
    for (int i = 0; i < 16; ++i) CP16(sbase + STAGE_B + doff[i], gp[i] + 64);
    asm volatile("cp.async.commit_group;" ::: "memory");
    asm volatile("cp.async.wait_group 0;" ::: "memory");
    __syncthreads();
    ld_frags(0, sbase, 0);

    for (int c = 0; c < NCH64; ++c) {
        const int slot = c % 3;
        const uint32_t st = sbase + slot * STAGE_B;

        if (c > 0) {
            asm volatile("cp.async.wait_group 0;" ::: "memory");
            __syncthreads();
        }
        if (c + 2 < NCH64) {
            uint32_t sb = sbase + ((c + 2) % 3) * STAGE_B;
            const size_t ko = (size_t)(c + 2) * 64;
#pragma unroll
            for (int i = 0; i < 16; ++i) CP16(sb + doff[i], gp[i] + ko);
            asm volatile("cp.async.commit_group;" ::: "memory");
        }

#pragma unroll
        for (int kk = 0; kk < 4; ++kk) {
            const int cb = kk & 1, nb = cb ^ 1;
            if (kk < 3) {
                ld_frags(nb, st, kk + 1);
            } else if (c + 1 < NCH64) {
                ld_frags(nb, sbase + ((c + 1) % 3) * STAGE_B, 0);
            }
#pragma unroll
            for (int mi = 0; mi < 4; ++mi)
#pragma unroll
                for (int nj = 0; nj < 2; ++nj) {
                    MMA16816(acc[mi][2 * nj],     ah[cb][mi], &bh[cb][nj][0]);
                    MMA16816(acc[mi][2 * nj + 1], ah[cb][mi], &bh[cb][nj][2]);
                }
#pragma unroll
            for (int mi = 0; mi < 4; ++mi)
#pragma unroll
                for (int nj = 0; nj < 2; ++nj) {
                    MMA16816(acc[mi][2 * nj],     ah[cb][mi], &bl[cb][nj][0]);
                    MMA16816(acc[mi][2 * nj + 1], ah[cb][mi], &bl[cb][nj][2]);
                }
#pragma unroll
            for (int mi = 0; mi < 4; ++mi)
#pragma unroll
                for (int nj = 0; nj < 2; ++nj) {
                    MMA16816(acc[mi][2 * nj],     al[cb][mi], &bh[cb][nj][0]);
                    MMA16816(acc[mi][2 * nj + 1], al[cb][mi], &bh[cb][nj][2]);
                }
        }
    }

    // ---- epilogue: bias + relu, out[(m>>5)*32768 + o*32 + (m&31)] ----
    const int g = lane >> 2, t = lane & 3;
#pragma unroll
    for (int mi = 0; mi < 4; ++mi) {
#pragma unroll
        for (int ni = 0; ni < 4; ++ni) {
            int mA = m0 + wm * 64 + mi * 16 + g;
            int oL = wn * 32 + ni * 8 + 2 * t;
            int oA = n0 + oL;
            float b0 = s_bias[oL], b1 = s_bias[oL + 1];
            float v;
            v = acc[mi][ni][0] + b0;
            out[(size_t)(mA >> 5) * 32768 + (size_t)oA * 32 + (mA & 31)] = v > 0.f ? v : 0.f;
            v = acc[mi][ni][1] + b1;
            out[(size_t)(mA >> 5) * 32768 + (size_t)(oA + 1) * 32 + (mA & 31)] = v > 0.f ? v : 0.f;
            int mB = mA + 8;
            v = acc[mi][ni][2] + b0;
            out[(size_t)(mB >> 5) * 32768 + (size_t)oA * 32 + (mB & 31)] = v > 0.f ? v : 0.f;
            v = acc[mi][ni][3] + b1;
            out[(size_t)(mB >> 5) * 32768 + (size_t)(oA + 1) * 32 + (mB & 31)] = v > 0.f ? v : 0.f;
        }
    }
}

// ---------------------------------------------------------------------------
extern "C" void kernel_launch(void* const* d_in, const int* in_sizes, int n_in,
                              void* d_out, int out_size) {
    const float* f1     = (const float*)d_in[0];   // [1024, 1024]
    const float* conv_w = (const float*)d_in[1];   // [1024, 1024, 16, 1]
    const float* conv_b = (const float*)d_in[2];   // [1024]
    float* out = (float*)d_out;                    // [1024, 2048]

    cudaFuncSetAttribute(hmma_gemm_kernel,
                         cudaFuncAttributeMaxDynamicSharedMemorySize, DSMEM_B);

    topk_kernel<<<NN, 1024>>>(f1);
    build_B_kernel<<<NN, 512>>>(conv_w);
    build_A_kernel<<<dim3(34, 64), 256>>>(f1);
    hmma_gemm_kernel<<<dim3(8, 16), 256, DSMEM_B>>>(conv_b, out);
    (void)in_sizes; (void)n_in; (void)out_size;
}

// round 17
// speedup vs baseline: 1.5486x; 1.5486x over previous
#include <cuda_runtime.h>
#include <cuda_bf16.h>
#include <cstdint>

#define NN 1024
#define TOPK 16
#define NPAIR 272           // 256 pos (c_hi,t) pairs + 16 rep c_hi slices
#define KK (NPAIR * 32)     // 8704
#define MM 2048             // (b, w)
#define NCH64 (KK / 64)     // 136 K-chunks of 64

// Scratch (device globals: allocation-free per harness rules)
__device__ int            g_row[NPAIR * 64];
__device__ __nv_bfloat16  g_Ah[(size_t)MM * KK];
__device__ __nv_bfloat16  g_Al[(size_t)MM * KK];
__device__ __nv_bfloat16  g_Bh[(size_t)NN * KK];
__device__ __nv_bfloat16  g_Bl[(size_t)NN * KK];

__device__ __forceinline__ uint32_t smem_u32(const void* p) {
    uint32_t a;
    asm("{ .reg .u64 t; cvta.to.shared.u64 t, %1; cvt.u32.u64 %0, t; }"
        : "=r"(a) : "l"(p));
    return a;
}
__device__ __forceinline__ void split_bf16(float x, __nv_bfloat16& h, __nv_bfloat16& l) {
    h = __float2bfloat16(x);
    l = __float2bfloat16(x - __bfloat162float(h));
}
__device__ __forceinline__ uint32_t pack_bf2(__nv_bfloat16 a, __nv_bfloat16 b) {
    __nv_bfloat162 v(a, b);
    return *(uint32_t*)&v;
}

// ---------------------------------------------------------------------------
// Kernel 1: exact top-16 per row (ties -> lowest index) + g_row emission.
// ---------------------------------------------------------------------------
__global__ __launch_bounds__(1024) void topk_kernel(const float* __restrict__ f1) {
    __shared__ float wv[32];
    __shared__ int   wi[32];
    __shared__ int   s_best;
    __shared__ int   s_idx[TOPK];
    const int n = blockIdx.x, tid = threadIdx.x;
    const int lane = tid & 31, w = tid >> 5;
    float v = f1[n * NN + tid];
    const float NEG_INF = __int_as_float(0xff800000);

    for (int it = 0; it < TOPK; ++it) {
        float rv = v; int ri = tid;
#pragma unroll
        for (int s = 16; s > 0; s >>= 1) {
            float ov = __shfl_down_sync(0xffffffffu, rv, s);
            int   oi = __shfl_down_sync(0xffffffffu, ri, s);
            if (ov > rv || (ov == rv && oi < ri)) { rv = ov; ri = oi; }
        }
        if (lane == 0) { wv[w] = rv; wi[w] = ri; }
        __syncthreads();
        if (w == 0) {
            float rv2 = wv[lane]; int ri2 = wi[lane];
#pragma unroll
            for (int s = 16; s > 0; s >>= 1) {
                float ov = __shfl_down_sync(0xffffffffu, rv2, s);
                int   oi = __shfl_down_sync(0xffffffffu, ri2, s);
                if (ov > rv2 || (ov == rv2 && oi < ri2)) { rv2 = ov; ri2 = oi; }
            }
            if (lane == 0) { s_idx[it] = ri2; s_best = ri2; }
        }
        __syncthreads();
        if (tid == s_best) v = NEG_INF;
    }
    const int b = n >> 4, c_hi = n & 15;
    if (tid < TOPK) g_row[(c_hi * 16 + tid) * 64 + b] = s_idx[tid];
    if (tid == TOPK) g_row[(256 + c_hi) * 64 + b] = n;
}

// ---------------------------------------------------------------------------
// Kernel 2: build split-bf16 B [NN, KK] K-major, float4 reads + 8B stores.
// ---------------------------------------------------------------------------
__global__ __launch_bounds__(512) void build_B_kernel(const float* __restrict__ conv_w) {
    const int o = blockIdx.x;
    const float* cw = conv_w + (size_t)o * 16384;
    for (int k0 = threadIdx.x * 4; k0 < KK; k0 += 2048) {
        int pair = k0 >> 5, j = k0 & 31, c2 = j >> 4, h = j & 15;
        float4 v;
        if (pair < 256) {
            int ch = pair >> 4, t = pair & 15;
            v = *(const float4*)(cw + (ch * 64 + t * 4 + 2 + c2) * 16 + h);
        } else {
            int ch = pair - 256;
            v = make_float4(0.f, 0.f, 0.f, 0.f);
#pragma unroll
            for (int t = 0; t < 16; ++t) {
                float4 u = *(const float4*)(cw + (ch * 64 + t * 4 + c2) * 16 + h);
                v.x += u.x; v.y += u.y; v.z += u.z; v.w += u.w;
            }
        }
        __nv_bfloat16 hh[4], ll[4];
        split_bf16(v.x, hh[0], ll[0]); split_bf16(v.y, hh[1], ll[1]);
        split_bf16(v.z, hh[2], ll[2]); split_bf16(v.w, hh[3], ll[3]);
        uint2 ph = make_uint2(pack_bf2(hh[0], hh[1]), pack_bf2(hh[2], hh[3]));
        uint2 pl = make_uint2(pack_bf2(ll[0], ll[1]), pack_bf2(ll[2], ll[3]));
        *(uint2*)&g_Bh[(size_t)o * KK + k0] = ph;
        *(uint2*)&g_Bl[(size_t)o * KK + k0] = pl;
    }
}

// ---------------------------------------------------------------------------
// Kernel 3: build split-bf16 A [MM, KK] K-major, coalesced 16B stores.
// ---------------------------------------------------------------------------
#define SP2 1056   // 32 * 33 floats per staged row

__global__ __launch_bounds__(256) void build_A_kernel(const float* __restrict__ f1) {
    __shared__ float s[8 * SP2];
    const int pg = blockIdx.x, b = blockIdx.y, t = threadIdx.x;
    {
        const int pi = t >> 5, c32 = t & 31;
        const int r = g_row[(pg * 8 + pi) * 64 + b];
        const float4* src = (const float4*)(f1 + (size_t)r * 1024);
        const int jb = c32 >> 3;
        const int w0 = (c32 & 7) * 4;
#pragma unroll
        for (int q = 0; q < 8; ++q) {
            float4 v = src[c32 + q * 32];
            float* dst = &s[pi * SP2 + (jb + 4 * q) * 33 + w0];
            dst[0] = v.x; dst[1] = v.y; dst[2] = v.z; dst[3] = v.w;
        }
    }
    __syncthreads();
    const int w = t >> 3, pp = (t >> 2) & 1, jc = t & 3, j0 = jc * 8;
#pragma unroll
    for (int q = 0; q < 4; ++q) {
        const int pi = q * 2 + pp;
        __nv_bfloat16 h[8], l[8];
#pragma unroll
        for (int d = 0; d < 8; ++d) {
            float v = s[pi * SP2 + (j0 + d) * 33 + w];
            split_bf16(v, h[d], l[d]);
        }
        uint4 ph = make_uint4(pack_bf2(h[0], h[1]), pack_bf2(h[2], h[3]),
                              pack_bf2(h[4], h[5]), pack_bf2(h[6], h[7]));
        uint4 pl = make_uint4(pack_bf2(l[0], l[1]), pack_bf2(l[2], l[3]),
                              pack_bf2(l[4], l[5]), pack_bf2(l[6], l[7]));
        const size_t dst = (size_t)(b * 32 + w) * KK + (pg * 8 + pi) * 32 + j0;
        *(uint4*)&g_Ah[dst] = ph;
        *(uint4*)&g_Al[dst] = pl;
    }
}

// ---------------------------------------------------------------------------
// Kernel 4: HMMA GEMM (locked best config, R12/R14).
// C = AhBh + AhBl + AlBh, bias+relu. CTA 128x128, 8 warps (2x4), warp 64x32,
// BK=64, 3-stage cp.async (batched 16 CP16 at chunk top), frag double-buffer
// + cross-chunk kk0 prefetch.
// ---------------------------------------------------------------------------
#define TILE_B 16384
#define STAGE_B 65536
#define DSMEM_B (3 * STAGE_B)

#define LDSM_X4(R, ADDR) \
    asm volatile("ldmatrix.sync.aligned.m8n8.x4.shared.b16 {%0,%1,%2,%3}, [%4];" \
        : "=r"((R)[0]), "=r"((R)[1]), "=r"((R)[2]), "=r"((R)[3]) : "r"(ADDR))
#define MMA16816(C, A, B) \
    asm volatile("mma.sync.aligned.m16n8k16.row.col.f32.bf16.bf16.f32 " \
        "{%0,%1,%2,%3}, {%4,%5,%6,%7}, {%8,%9}, {%0,%1,%2,%3};" \
        : "+f"((C)[0]), "+f"((C)[1]), "+f"((C)[2]), "+f"((C)[3]) \
        : "r"((A)[0]), "r"((A)[1]), "r"((A)[2]), "r"((A)[3]), \
          "r"((B)[0]), "r"((B)[1]))
#define CP16(DST, SRC) \
    asm volatile("cp.async.cg.shared.global [%0], [%1], 16;" \
        :: "r"(DST), "l"(SRC) : "memory")

__global__ __launch_bounds__(256, 1) void hmma_gemm_kernel(
    const float* __restrict__ conv_b, float* __restrict__ out) {
    extern __shared__ __align__(128) char dsm[];
    __shared__ float s_bias[128];

    const int tid = threadIdx.x, lane = tid & 31, wid = tid >> 5;
    const int m0 = blockIdx.y * 128, n0 = blockIdx.x * 128;
    const int wm = wid >> 2, wn = wid & 3;
    const uint32_t sbase = smem_u32(dsm);
    if (tid < 128) s_bias[tid] = conv_b[n0 + tid];

    // ---- cp.async mapping: 16 x 16B chunks per thread per stage ----
    const __nv_bfloat16* gp[16];
    uint32_t doff[16];
#pragma unroll
    for (int i = 0; i < 16; ++i) {
        int cid = tid + i * 256;
        int tile = cid >> 10, row = (cid >> 3) & 127, ch = cid & 7;
        const __nv_bfloat16* base =
            (tile == 0) ? g_Ah + (size_t)(m0 + row) * KK :
            (tile == 1) ? g_Al + (size_t)(m0 + row) * KK :
            (tile == 2) ? g_Bh + (size_t)(n0 + row) * KK :
                          g_Bl + (size_t)(n0 + row) * KK;
        gp[i] = base + ch * 8;
        doff[i] = tile * TILE_B + row * 128 + ((ch ^ (row & 7)) * 16);
    }

    // ---- ldmatrix lane constants ----
    const int aq  = lane >> 3;
    const int aml = wm * 64 + (aq & 1) * 8 + (lane & 7);
    const int acp = aq >> 1;
    const int as  = aml & 7;
    const int bnl4 = wn * 32 + ((lane >> 4) & 1) * 8 + (lane & 7);
    const int bq4  = (lane >> 3) & 1;
    const int bs4  = bnl4 & 7;

    float acc[4][4][4];
#pragma unroll
    for (int mi = 0; mi < 4; ++mi)
#pragma unroll
        for (int ni = 0; ni < 4; ++ni)
#pragma unroll
            for (int r = 0; r < 4; ++r) acc[mi][ni][r] = 0.f;

    uint32_t ah[2][4][4], al[2][4][4], bh[2][2][4], bl[2][2][4];

    auto ld_frags = [&](int fb, uint32_t st, int kk) {
        const uint32_t aoff = aml * 128 + (((kk * 2 + acp) ^ as) * 16);
        const uint32_t boff = bnl4 * 128 + (((kk * 2 + bq4) ^ bs4) * 16);
#pragma unroll
        for (int mi = 0; mi < 4; ++mi) LDSM_X4(ah[fb][mi], st + aoff + mi * 2048);
#pragma unroll
        for (int mi = 0; mi < 4; ++mi) LDSM_X4(al[fb][mi], st + TILE_B + aoff + mi * 2048);
#pragma unroll
        for (int nj = 0; nj < 2; ++nj) LDSM_X4(bh[fb][nj], st + 2 * TILE_B + boff + nj * 2048);
#pragma unroll
        for (int nj = 0; nj < 2; ++nj) LDSM_X4(bl[fb][nj], st + 3 * TILE_B + boff + nj * 2048);
    };

    // ---- prologue: stages 0 and 1; wait for BOTH (kk3 of chunk 0 prefetches
    //      chunk 1 kk0 from stage 1, so stage 1 must be complete) ----
#pragma unroll
    for (int i = 0; i < 16; ++i) CP16(sbase + doff[i], gp[i]);
    asm volatile("cp.async.commit_group;" ::: "memory");
#pragma unroll
    for (int i = 0; i < 16; ++i) CP16(sbase + STAGE_B + doff[i], gp[i] + 64);
    asm volatile("cp.async.commit_group;" ::: "memory");
    asm volatile("cp.async.wait_group 0;" ::: "memory");
    __syncthreads();
    ld_frags(0, sbase, 0);

    for (int c = 0; c < NCH64; ++c) {
        const int slot = c % 3;
        const uint32_t st = sbase + slot * STAGE_B;

        if (c > 0) {
            asm volatile("cp.async.wait_group 0;" ::: "memory");
            __syncthreads();
        }
        if (c + 2 < NCH64) {
            uint32_t sb = sbase + ((c + 2) % 3) * STAGE_B;
            const size_t ko = (size_t)(c + 2) * 64;
#pragma unroll
            for (int i = 0; i < 16; ++i) CP16(sb + doff[i], gp[i] + ko);
            asm volatile("cp.async.commit_group;" ::: "memory");
        }

#pragma unroll
        for (int kk = 0; kk < 4; ++kk) {
            const int cb = kk & 1, nb = cb ^ 1;
            if (kk < 3) {
                ld_frags(nb, st, kk + 1);
            } else if (c + 1 < NCH64) {
                ld_frags(nb, sbase + ((c + 1) % 3) * STAGE_B, 0);
            }
#pragma unroll
            for (int mi = 0; mi < 4; ++mi)
#pragma unroll
                for (int nj = 0; nj < 2; ++nj) {
                    MMA16816(acc[mi][2 * nj],     ah[cb][mi], &bh[cb][nj][0]);
                    MMA16816(acc[mi][2 * nj + 1], ah[cb][mi], &bh[cb][nj][2]);
                }
#pragma unroll
            for (int mi = 0; mi < 4; ++mi)
#pragma unroll
                for (int nj = 0; nj < 2; ++nj) {
                    MMA16816(acc[mi][2 * nj],     ah[cb][mi], &bl[cb][nj][0]);
                    MMA16816(acc[mi][2 * nj + 1], ah[cb][mi], &bl[cb][nj][2]);
                }
#pragma unroll
            for (int mi = 0; mi < 4; ++mi)
#pragma unroll
                for (int nj = 0; nj < 2; ++nj) {
                    MMA16816(acc[mi][2 * nj],     al[cb][mi], &bh[cb][nj][0]);
                    MMA16816(acc[mi][2 * nj + 1], al[cb][mi], &bh[cb][nj][2]);
                }
        }
    }

    // ---- epilogue: bias + relu, out[(m>>5)*32768 + o*32 + (m&31)] ----
    const int g = lane >> 2, t = lane & 3;
#pragma unroll
    for (int mi = 0; mi < 4; ++mi) {
#pragma unroll
        for (int ni = 0; ni < 4; ++ni) {
            int mA = m0 + wm * 64 + mi * 16 + g;
            int oL = wn * 32 + ni * 8 + 2 * t;
            int oA = n0 + oL;
            float b0 = s_bias[oL], b1 = s_bias[oL + 1];
            float v;
            v = acc[mi][ni][0] + b0;
            out[(size_t)(mA >> 5) * 32768 + (size_t)oA * 32 + (mA & 31)] = v > 0.f ? v : 0.f;
            v = acc[mi][ni][1] + b1;
            out[(size_t)(mA >> 5) * 32768 + (size_t)(oA + 1) * 32 + (mA & 31)] = v > 0.f ? v : 0.f;
            int mB = mA + 8;
            v = acc[mi][ni][2] + b0;
            out[(size_t)(mB >> 5) * 32768 + (size_t)oA * 32 + (mB & 31)] = v > 0.f ? v : 0.f;
            v = acc[mi][ni][3] + b1;
            out[(size_t)(mB >> 5) * 32768 + (size_t)(oA + 1) * 32 + (mB & 31)] = v > 0.f ? v : 0.f;
        }
    }
}

// ---------------------------------------------------------------------------
extern "C" void kernel_launch(void* const* d_in, const int* in_sizes, int n_in,
                              void* d_out, int out_size) {
    const float* f1     = (const float*)d_in[0];   // [1024, 1024]
    const float* conv_w = (const float*)d_in[1];   // [1024, 1024, 16, 1]
    const float* conv_b = (const float*)d_in[2];   // [1024]
    float* out = (float*)d_out;                    // [1024, 2048]

    cudaFuncSetAttribute(hmma_gemm_kernel,
                         cudaFuncAttributeMaxDynamicSharedMemorySize, DSMEM_B);

    topk_kernel<<<NN, 1024>>>(f1);
    build_B_kernel<<<NN, 512>>>(conv_w);
    build_A_kernel<<<dim3(34, 64), 256>>>(f1);
    hmma_gemm_kernel<<<dim3(8, 16), 256, DSMEM_B>>>(conv_b, out);
    (void)in_sizes; (void)n_in; (void)out_size;
}